// round 16
// baseline (speedup 1.0000x reference)
#include <cuda_runtime.h>

// KL( N(pm, diag(ps^2)) || N(qm, diag(qs^2)) ), summed over N,D, mean over B,L.
// Per element: 0.5*(r^2 + d^2 - 1 - 2 ln r), r = ps/qs, d = (qm-pm)/qs.
// Total = 0.5*S2 - 0.5*n - ln2*SL, where S2 = sum(r^2+d^2), SL = sum lg2(r)
// (logs batched: one lg2 per product of 4 ratios; product of 4 ratios in
// [1/81,81] so lg2.approx error is negligible vs 1e-3 tolerance).
// Mean divisor = B*L = n/(N*D).
//
// Single fused kernel: per-block partials -> threadfence-reduction pattern,
// last-arriving block reduces the 1184 L2-resident partials and finalizes.
// Counter self-resets to 0 so every call sees identical initial state
// (bit-deterministic: fixed partial set, fixed reduction order).

#define NTHREADS 256
#define NBLOCKS  1184          // 148 SMs * 8
#define ND_F     2048.0f       // N*D = 32*64

__device__ float2   g_part[NBLOCKS];
__device__ unsigned g_count = 0;

static __device__ __forceinline__ float frcp(float x) {
    float r; asm("rcp.approx.ftz.f32 %0, %1;" : "=f"(r) : "f"(x)); return r;
}
static __device__ __forceinline__ float flg2(float x) {
    float r; asm("lg2.approx.ftz.f32 %0, %1;" : "=f"(r) : "f"(x)); return r;
}

__global__ void __launch_bounds__(NTHREADS)
kl_fused(const float4* __restrict__ pm, const float4* __restrict__ ps,
         const float4* __restrict__ qm, const float4* __restrict__ qs,
         float* __restrict__ out, int n4, int n)
{
    float s2 = 0.0f;   // sum of ratio^2 + diff^2
    float sl = 0.0f;   // sum of lg2(ratio), batched by 4
    const int stride = gridDim.x * blockDim.x;

    for (int i = blockIdx.x * blockDim.x + threadIdx.x; i < n4; i += stride) {
        float4 mp = pm[i];
        float4 sp = ps[i];
        float4 mq = qm[i];
        float4 sq = qs[i];

        float i0 = frcp(sq.x), i1 = frcp(sq.y), i2 = frcp(sq.z), i3 = frcp(sq.w);

        float r0 = sp.x * i0, r1 = sp.y * i1, r2 = sp.z * i2, r3 = sp.w * i3;
        float d0 = (mq.x - mp.x) * i0;
        float d1 = (mq.y - mp.y) * i1;
        float d2 = (mq.z - mp.z) * i2;
        float d3 = (mq.w - mp.w) * i3;

        s2 = fmaf(r0, r0, s2);
        s2 = fmaf(r1, r1, s2);
        s2 = fmaf(r2, r2, s2);
        s2 = fmaf(r3, r3, s2);
        s2 = fmaf(d0, d0, s2);
        s2 = fmaf(d1, d1, s2);
        s2 = fmaf(d2, d2, s2);
        s2 = fmaf(d3, d3, s2);

        sl += flg2((r0 * r1) * (r2 * r3));   // 1 MUFU LG2 per 4 elements
    }

    // ---- intra-block reduce ----
    #pragma unroll
    for (int off = 16; off > 0; off >>= 1) {
        s2 += __shfl_xor_sync(0xffffffffu, s2, off);
        sl += __shfl_xor_sync(0xffffffffu, sl, off);
    }

    __shared__ float sh2[NTHREADS / 32];
    __shared__ float shl[NTHREADS / 32];
    int wid  = threadIdx.x >> 5;
    int lane = threadIdx.x & 31;
    if (lane == 0) { sh2[wid] = s2; shl[wid] = sl; }
    __syncthreads();

    if (threadIdx.x < (NTHREADS / 32)) {
        s2 = sh2[threadIdx.x];
        sl = shl[threadIdx.x];
        #pragma unroll
        for (int off = (NTHREADS / 64); off > 0; off >>= 1) {
            s2 += __shfl_xor_sync((1u << (NTHREADS / 32)) - 1u, s2, off);
            sl += __shfl_xor_sync((1u << (NTHREADS / 32)) - 1u, sl, off);
        }
        if (threadIdx.x == 0) g_part[blockIdx.x] = make_float2(s2, sl);
    }

    // ---- threadfence reduction: last block finalizes ----
    __shared__ unsigned is_last;
    __threadfence();                       // make g_part write visible device-wide
    if (threadIdx.x == 0) {
        unsigned c = atomicAdd(&g_count, 1u);
        is_last = (c == (unsigned)gridDim.x - 1u) ? 1u : 0u;
    }
    __syncthreads();

    if (is_last) {
        float t2 = 0.0f, tl = 0.0f;
        for (int i = threadIdx.x; i < NBLOCKS; i += NTHREADS) {
            float2 p = g_part[i];          // all L2-resident at this point
            t2 += p.x;
            tl += p.y;
        }
        #pragma unroll
        for (int off = 16; off > 0; off >>= 1) {
            t2 += __shfl_xor_sync(0xffffffffu, t2, off);
            tl += __shfl_xor_sync(0xffffffffu, tl, off);
        }
        if (lane == 0) { sh2[wid] = t2; shl[wid] = tl; }
        __syncthreads();
        if (threadIdx.x == 0) {
            t2 = 0.0f; tl = 0.0f;
            #pragma unroll
            for (int w = 0; w < NTHREADS / 32; w++) { t2 += sh2[w]; tl += shl[w]; }
            const float LN2 = 0.69314718055994530942f;
            float total = 0.5f * t2 - 0.5f * (float)n - LN2 * tl;
            out[0] = total * (ND_F / (float)n);   // divide by B*L = n / (N*D)
            g_count = 0;                   // reset for next (graph-replayed) call
        }
    }
}

extern "C" void kernel_launch(void* const* d_in, const int* in_sizes, int n_in,
                              void* d_out, int out_size)
{
    const float4* pm = (const float4*)d_in[0];  // prior_mu
    const float4* ps = (const float4*)d_in[1];  // prior_sigma
    const float4* qm = (const float4*)d_in[2];  // post_mu
    const float4* qs = (const float4*)d_in[3];  // post_sigma
    int n = in_sizes[0];                         // B*L*N*D (divisible by 4)

    kl_fused<<<NBLOCKS, NTHREADS>>>(pm, ps, qm, qs, (float*)d_out, n >> 2, n);
}

// round 17
// speedup vs baseline: 1.0377x; 1.0377x over previous
#include <cuda_runtime.h>

// KL( N(pm, diag(ps^2)) || N(qm, diag(qs^2)) ), summed over N,D, mean over B,L.
// Per element: 0.5*(r^2 + d^2 - 1 - 2 ln r), r = ps/qs, d = (qm-pm)/qs.
// Total = 0.5*S2 - 0.5*n - ln2*SL, where S2 = sum(r^2+d^2), SL = sum lg2(r)
// (logs batched: one lg2 per product of 4 ratios; product in [1/81,81] so
// lg2.approx error is negligible vs 1e-3 tolerance). Mean divisor = B*L = n/(N*D).
//
// Memory-roofline version: 8 LDG.128 front-batched per iteration (2 float4s
// per tensor), streaming (.cs) loads, 4 CTAs/SM. Single fused kernel with
// threadfence-reduction tail (deterministic: fixed partial set + fixed order;
// the counter atomic only elects the last block).

#define NTHREADS 256
#define NBLOCKS  592           // 148 SMs * 4
#define ND_F     2048.0f       // N*D = 32*64

__device__ float2   g_part[NBLOCKS];
__device__ unsigned g_count = 0;

static __device__ __forceinline__ float frcp(float x) {
    float r; asm("rcp.approx.ftz.f32 %0, %1;" : "=f"(r) : "f"(x)); return r;
}
static __device__ __forceinline__ float flg2(float x) {
    float r; asm("lg2.approx.ftz.f32 %0, %1;" : "=f"(r) : "f"(x)); return r;
}

__global__ void __launch_bounds__(NTHREADS)
kl_fused(const float4* __restrict__ pm, const float4* __restrict__ ps,
         const float4* __restrict__ qm, const float4* __restrict__ qs,
         float* __restrict__ out, int n8, int n)
{
    float s2a = 0.0f, s2b = 0.0f;   // sum of ratio^2 + diff^2 (two chains)
    float sl  = 0.0f;               // sum of lg2(ratio), batched by 4
    const int stride = NBLOCKS * NTHREADS;

    for (int i = blockIdx.x * NTHREADS + threadIdx.x; i < n8; i += stride) {
        int j = i << 1;             // two adjacent float4s per tensor
        // ---- 8 streaming LDG.128 issued before any math ----
        float4 sqA = __ldcs(qs + j);
        float4 sqB = __ldcs(qs + j + 1);
        float4 spA = __ldcs(ps + j);
        float4 spB = __ldcs(ps + j + 1);
        float4 mqA = __ldcs(qm + j);
        float4 mqB = __ldcs(qm + j + 1);
        float4 mpA = __ldcs(pm + j);
        float4 mpB = __ldcs(pm + j + 1);

        float iA0 = frcp(sqA.x), iA1 = frcp(sqA.y), iA2 = frcp(sqA.z), iA3 = frcp(sqA.w);
        float iB0 = frcp(sqB.x), iB1 = frcp(sqB.y), iB2 = frcp(sqB.z), iB3 = frcp(sqB.w);

        float rA0 = spA.x * iA0, rA1 = spA.y * iA1, rA2 = spA.z * iA2, rA3 = spA.w * iA3;
        float rB0 = spB.x * iB0, rB1 = spB.y * iB1, rB2 = spB.z * iB2, rB3 = spB.w * iB3;

        float dA0 = (mqA.x - mpA.x) * iA0;
        float dA1 = (mqA.y - mpA.y) * iA1;
        float dA2 = (mqA.z - mpA.z) * iA2;
        float dA3 = (mqA.w - mpA.w) * iA3;
        float dB0 = (mqB.x - mpB.x) * iB0;
        float dB1 = (mqB.y - mpB.y) * iB1;
        float dB2 = (mqB.z - mpB.z) * iB2;
        float dB3 = (mqB.w - mpB.w) * iB3;

        s2a = fmaf(rA0, rA0, s2a);  s2b = fmaf(rB0, rB0, s2b);
        s2a = fmaf(rA1, rA1, s2a);  s2b = fmaf(rB1, rB1, s2b);
        s2a = fmaf(rA2, rA2, s2a);  s2b = fmaf(rB2, rB2, s2b);
        s2a = fmaf(rA3, rA3, s2a);  s2b = fmaf(rB3, rB3, s2b);
        s2a = fmaf(dA0, dA0, s2a);  s2b = fmaf(dB0, dB0, s2b);
        s2a = fmaf(dA1, dA1, s2a);  s2b = fmaf(dB1, dB1, s2b);
        s2a = fmaf(dA2, dA2, s2a);  s2b = fmaf(dB2, dB2, s2b);
        s2a = fmaf(dA3, dA3, s2a);  s2b = fmaf(dB3, dB3, s2b);

        sl += flg2((rA0 * rA1) * (rA2 * rA3));   // 1 MUFU LG2 per 4 elems
        sl += flg2((rB0 * rB1) * (rB2 * rB3));
    }

    float s2 = s2a + s2b;

    // ---- intra-block reduce ----
    #pragma unroll
    for (int off = 16; off > 0; off >>= 1) {
        s2 += __shfl_xor_sync(0xffffffffu, s2, off);
        sl += __shfl_xor_sync(0xffffffffu, sl, off);
    }

    __shared__ float sh2[NTHREADS / 32];
    __shared__ float shl[NTHREADS / 32];
    int wid  = threadIdx.x >> 5;
    int lane = threadIdx.x & 31;
    if (lane == 0) { sh2[wid] = s2; shl[wid] = sl; }
    __syncthreads();

    // ---- per-block partial + last-block finalize ----
    __shared__ unsigned is_last;
    if (threadIdx.x == 0) {
        s2 = 0.0f; sl = 0.0f;
        #pragma unroll
        for (int w = 0; w < NTHREADS / 32; w++) { s2 += sh2[w]; sl += shl[w]; }
        g_part[blockIdx.x] = make_float2(s2, sl);
        __threadfence();                  // order partial before the count
        unsigned c = atomicAdd(&g_count, 1u);
        is_last = (c == (unsigned)NBLOCKS - 1u) ? 1u : 0u;
    }
    __syncthreads();

    if (is_last) {
        float t2 = 0.0f, tl = 0.0f;
        for (int i = threadIdx.x; i < NBLOCKS; i += NTHREADS) {
            float2 p = g_part[i];         // L2-resident
            t2 += p.x;
            tl += p.y;
        }
        #pragma unroll
        for (int off = 16; off > 0; off >>= 1) {
            t2 += __shfl_xor_sync(0xffffffffu, t2, off);
            tl += __shfl_xor_sync(0xffffffffu, tl, off);
        }
        if (lane == 0) { sh2[wid] = t2; shl[wid] = tl; }
        __syncthreads();
        if (threadIdx.x == 0) {
            t2 = 0.0f; tl = 0.0f;
            #pragma unroll
            for (int w = 0; w < NTHREADS / 32; w++) { t2 += sh2[w]; tl += shl[w]; }
            const float LN2 = 0.69314718055994530942f;
            float total = 0.5f * t2 - 0.5f * (float)n - LN2 * tl;
            out[0] = total * (ND_F / (float)n);   // divide by B*L = n / (N*D)
            g_count = 0;                  // reset for next graph replay
        }
    }
}

extern "C" void kernel_launch(void* const* d_in, const int* in_sizes, int n_in,
                              void* d_out, int out_size)
{
    const float4* pm = (const float4*)d_in[0];  // prior_mu
    const float4* ps = (const float4*)d_in[1];  // prior_sigma
    const float4* qm = (const float4*)d_in[2];  // post_mu
    const float4* qs = (const float4*)d_in[3];  // post_sigma
    int n = in_sizes[0];                         // B*L*N*D (divisible by 8)

    kl_fused<<<NBLOCKS, NTHREADS>>>(pm, ps, qm, qs, (float*)d_out, n >> 3, n);
}